// round 3
// baseline (speedup 1.0000x reference)
#include <cuda_runtime.h>
#include <mma.h>
#include <math.h>
using namespace nvcuda;

#define BB 4
#define TT 1024
#define MM 512
#define HH 8
#define DK 64
#define DV 64
#define NTOK (BB*TT)          // 4096
#define PROJ (HH*DK)          // 512

__device__ float g_qf[NTOK*PROJ];
__device__ float g_kf[NTOK*PROJ];
__device__ float g_v [NTOK*PROJ];
__device__ float g_o [NTOK*PROJ];
__device__ float g_inv[BB*HH*TT];

enum { MODE_PHI = 0, MODE_RAW = 1 };

// ---------------------------------------------------------------------------
// Double-buffered TF32 GEMM: C[4096,512] = A[4096,512] @ W[512,512] + epilogue.
// BM=128, BN=64, BK=32, 256 thr, warp tile 32x32. grid.z selects problem.
// ---------------------------------------------------------------------------
#define LDA 40
#define LDB 72
#define LDC 72
#define GSMEM ((2*128*LDA + 2*32*LDB) * 4)   // 59392 B

__global__ __launch_bounds__(256, 2) void gemm_db(
    const float* __restrict__ A0, const float* __restrict__ W0,
    float* __restrict__ C0, int mode0,
    const float* __restrict__ A1, const float* __restrict__ W1,
    float* __restrict__ C1, int mode1)
{
    extern __shared__ float sm[];
    float* Abuf[2] = { sm, sm + 128 * LDA };
    float* Bbuf[2] = { sm + 2 * 128 * LDA, sm + 2 * 128 * LDA + 32 * LDB };
    float (*Cs)[LDC] = (float(*)[LDC])sm;   // alias after k-loop

    const float* A; const float* W; float* C; int mode;
    if (blockIdx.z == 0) { A = A0; W = W0; C = C0; mode = mode0; }
    else                 { A = A1; W = W1; C = C1; mode = mode1; }

    const int tid = threadIdx.x;
    const int wid = tid >> 5;
    const int wr = wid >> 1, wc = wid & 1;
    const int row0 = blockIdx.y * 128;
    const int col0 = blockIdx.x * 64;

    const int aR = tid >> 3, aC = (tid & 7) * 4;
    const int bR = tid >> 4, bC = (tid & 15) * 4;

    wmma::fragment<wmma::accumulator, 16, 16, 8, float> acc[2][2];
    #pragma unroll
    for (int i = 0; i < 2; i++)
        #pragma unroll
        for (int j = 0; j < 2; j++) wmma::fill_fragment(acc[i][j], 0.f);

    float4 pa[4], pb[2];
    #define LOAD_G(k0) { \
        _Pragma("unroll") \
        for (int p = 0; p < 4; p++) \
            pa[p] = *(const float4*)(A + (size_t)(row0 + aR + p * 32) * MM + (k0) + aC); \
        _Pragma("unroll") \
        for (int p = 0; p < 2; p++) \
            pb[p] = *(const float4*)(W + (size_t)((k0) + bR + p * 16) * PROJ + col0 + bC); }
    #define STORE_S(buf) { \
        float* As_ = Abuf[buf]; float* Bs_ = Bbuf[buf]; \
        _Pragma("unroll") \
        for (int p = 0; p < 4; p++) { \
            float* d = As_ + (aR + p * 32) * LDA + aC; \
            d[0] = wmma::__float_to_tf32(pa[p].x); d[1] = wmma::__float_to_tf32(pa[p].y); \
            d[2] = wmma::__float_to_tf32(pa[p].z); d[3] = wmma::__float_to_tf32(pa[p].w); } \
        _Pragma("unroll") \
        for (int p = 0; p < 2; p++) { \
            float* d = Bs_ + (bR + p * 16) * LDB + bC; \
            d[0] = wmma::__float_to_tf32(pb[p].x); d[1] = wmma::__float_to_tf32(pb[p].y); \
            d[2] = wmma::__float_to_tf32(pb[p].z); d[3] = wmma::__float_to_tf32(pb[p].w); } }

    LOAD_G(0); STORE_S(0); __syncthreads();
    int buf = 0;
    const int NTILE = MM / 32;   // 16
    for (int t = 0; t < NTILE; t++) {
        if (t + 1 < NTILE) LOAD_G((t + 1) * 32);
        float* As_ = Abuf[buf]; float* Bs_ = Bbuf[buf];
        #pragma unroll
        for (int kk = 0; kk < 32; kk += 8) {
            wmma::fragment<wmma::matrix_a, 16, 16, 8, wmma::precision::tf32, wmma::row_major> af[2];
            wmma::fragment<wmma::matrix_b, 16, 16, 8, wmma::precision::tf32, wmma::row_major> bf[2];
            #pragma unroll
            for (int i = 0; i < 2; i++)
                wmma::load_matrix_sync(af[i], As_ + (wr * 32 + i * 16) * LDA + kk, LDA);
            #pragma unroll
            for (int j = 0; j < 2; j++)
                wmma::load_matrix_sync(bf[j], Bs_ + kk * LDB + wc * 32 + j * 16, LDB);
            #pragma unroll
            for (int i = 0; i < 2; i++)
                #pragma unroll
                for (int j = 0; j < 2; j++)
                    wmma::mma_sync(acc[i][j], af[i], bf[j], acc[i][j]);
        }
        if (t + 1 < NTILE) STORE_S(buf ^ 1);
        __syncthreads();
        buf ^= 1;
    }

    #pragma unroll
    for (int i = 0; i < 2; i++)
        #pragma unroll
        for (int j = 0; j < 2; j++)
            wmma::store_matrix_sync(&Cs[wr * 32 + i * 16][wc * 32 + j * 16],
                                    acc[i][j], LDC, wmma::mem_row_major);
    __syncthreads();

    for (int e = tid; e < 128 * 16; e += 256) {
        int r = e >> 4, c = (e & 15) * 4;
        float4 v = *(float4*)&Cs[r][c];
        if (mode == MODE_PHI) {
            v.x = (v.x > 0.f) ? v.x + 1.f : expf(v.x);
            v.y = (v.y > 0.f) ? v.y + 1.f : expf(v.y);
            v.z = (v.z > 0.f) ? v.z + 1.f : expf(v.z);
            v.w = (v.w > 0.f) ? v.w + 1.f : expf(v.w);
        }
        *(float4*)(C + (size_t)(row0 + r) * PROJ + col0 + c) = v;
    }
    #undef LOAD_G
    #undef STORE_S
}

// ---------------------------------------------------------------------------
// Fused V + gate projection: vg = (value@Wv) * 2*sigmoid(value@Wg + bg).
// BM=64, BN=64, BK=32, 256 thr, dual accumulators, double buffered.
// ---------------------------------------------------------------------------
#define VSMEM ((2*(64*LDA + 2*32*LDB)) * 4)   // 57344 B

__global__ __launch_bounds__(256, 2) void gemm_vg(
    const float* __restrict__ A, const float* __restrict__ Wv,
    const float* __restrict__ Wg, const float* __restrict__ bg,
    float* __restrict__ C)
{
    extern __shared__ float sm[];
    const int HB = 64 * LDA + 2 * 32 * LDB;
    float* Abuf[2] = { sm, sm + HB };
    float* Vbuf[2] = { sm + 64 * LDA, sm + HB + 64 * LDA };
    float* Gbuf[2] = { sm + 64 * LDA + 32 * LDB, sm + HB + 64 * LDA + 32 * LDB };
    float (*Csv)[LDC] = (float(*)[LDC])sm;
    float (*Csg)[LDC] = (float(*)[LDC])(sm + 64 * LDC);

    const int tid = threadIdx.x;
    const int wid = tid >> 5;
    const int wr = wid >> 1, wc = wid & 1;   // wr 0..3 (16 rows), wc 0..1 (32 cols)
    const int row0 = blockIdx.y * 64;
    const int col0 = blockIdx.x * 64;

    const int aR = tid >> 3, aC = (tid & 7) * 4;      // 32 rows x 32 cols / pass (2 passes)
    const int bR = tid >> 4, bC = (tid & 15) * 4;     // 16 rows x 64 cols / pass (2 passes)

    wmma::fragment<wmma::accumulator, 16, 16, 8, float> accv[2], accg[2];
    #pragma unroll
    for (int j = 0; j < 2; j++) { wmma::fill_fragment(accv[j], 0.f); wmma::fill_fragment(accg[j], 0.f); }

    float4 pa[2], pv[2], pg[2];
    #define VG_LOAD(k0) { \
        _Pragma("unroll") \
        for (int p = 0; p < 2; p++) { \
            pa[p] = *(const float4*)(A  + (size_t)(row0 + aR + p * 32) * MM + (k0) + aC); \
            pv[p] = *(const float4*)(Wv + (size_t)((k0) + bR + p * 16) * PROJ + col0 + bC); \
            pg[p] = *(const float4*)(Wg + (size_t)((k0) + bR + p * 16) * PROJ + col0 + bC); } }
    #define VG_STORE(buf) { \
        _Pragma("unroll") \
        for (int p = 0; p < 2; p++) { \
            float* d = Abuf[buf] + (aR + p * 32) * LDA + aC; \
            d[0]=wmma::__float_to_tf32(pa[p].x); d[1]=wmma::__float_to_tf32(pa[p].y); \
            d[2]=wmma::__float_to_tf32(pa[p].z); d[3]=wmma::__float_to_tf32(pa[p].w); \
            float* dv = Vbuf[buf] + (bR + p * 16) * LDB + bC; \
            dv[0]=wmma::__float_to_tf32(pv[p].x); dv[1]=wmma::__float_to_tf32(pv[p].y); \
            dv[2]=wmma::__float_to_tf32(pv[p].z); dv[3]=wmma::__float_to_tf32(pv[p].w); \
            float* dg = Gbuf[buf] + (bR + p * 16) * LDB + bC; \
            dg[0]=wmma::__float_to_tf32(pg[p].x); dg[1]=wmma::__float_to_tf32(pg[p].y); \
            dg[2]=wmma::__float_to_tf32(pg[p].z); dg[3]=wmma::__float_to_tf32(pg[p].w); } }

    VG_LOAD(0); VG_STORE(0); __syncthreads();
    int buf = 0;
    const int NTILE = MM / 32;
    for (int t = 0; t < NTILE; t++) {
        if (t + 1 < NTILE) VG_LOAD((t + 1) * 32);
        float* As_ = Abuf[buf];
        #pragma unroll
        for (int kk = 0; kk < 32; kk += 8) {
            wmma::fragment<wmma::matrix_a, 16, 16, 8, wmma::precision::tf32, wmma::row_major> af;
            wmma::fragment<wmma::matrix_b, 16, 16, 8, wmma::precision::tf32, wmma::row_major> bfv[2], bfg[2];
            wmma::load_matrix_sync(af, As_ + (wr * 16) * LDA + kk, LDA);
            #pragma unroll
            for (int j = 0; j < 2; j++) {
                wmma::load_matrix_sync(bfv[j], Vbuf[buf] + kk * LDB + wc * 32 + j * 16, LDB);
                wmma::load_matrix_sync(bfg[j], Gbuf[buf] + kk * LDB + wc * 32 + j * 16, LDB);
            }
            #pragma unroll
            for (int j = 0; j < 2; j++) {
                wmma::mma_sync(accv[j], af, bfv[j], accv[j]);
                wmma::mma_sync(accg[j], af, bfg[j], accg[j]);
            }
        }
        if (t + 1 < NTILE) VG_STORE(buf ^ 1);
        __syncthreads();
        buf ^= 1;
    }

    #pragma unroll
    for (int j = 0; j < 2; j++) {
        wmma::store_matrix_sync(&Csv[wr * 16][wc * 32 + j * 16], accv[j], LDC, wmma::mem_row_major);
        wmma::store_matrix_sync(&Csg[wr * 16][wc * 32 + j * 16], accg[j], LDC, wmma::mem_row_major);
    }
    __syncthreads();

    for (int e = tid; e < 64 * 16; e += 256) {
        int r = e >> 4, c = (e & 15) * 4;
        float4 v = *(float4*)&Csv[r][c];
        float4 g = *(float4*)&Csg[r][c];
        v.x *= 2.f / (1.f + expf(-(g.x + bg[col0 + c + 0])));
        v.y *= 2.f / (1.f + expf(-(g.y + bg[col0 + c + 1])));
        v.z *= 2.f / (1.f + expf(-(g.z + bg[col0 + c + 2])));
        v.w *= 2.f / (1.f + expf(-(g.w + bg[col0 + c + 3])));
        *(float4*)(C + (size_t)(row0 + r) * PROJ + col0 + c) = v;
    }
    #undef VG_LOAD
    #undef VG_STORE
}

// ---------------------------------------------------------------------------
// Denominators: inv[t] = 1/(qf[t] . cumsum_t(kf) + eps), fp32 exact.
// One block per (b,h), 64 threads (one per k-dim).
// ---------------------------------------------------------------------------
__global__ __launch_bounds__(64) void denom_k(
    const float* __restrict__ qf, const float* __restrict__ kf,
    float* __restrict__ invd)
{
    __shared__ float cum[64][65];
    __shared__ float qs[64][65];
    const int bh = blockIdx.x;
    const int b = bh >> 3, h = bh & 7;
    const int j = threadIdx.x;
    float run = 0.f;
    for (int tile = 0; tile < 16; tile++) {
        const int t0 = tile * 64;
        #pragma unroll 8
        for (int r = 0; r < 64; r++) {
            size_t base = ((size_t)(b * TT + t0 + r)) * PROJ + h * DK + j;
            qs[r][j] = qf[base];
            run += kf[base];
            cum[r][j] = run;
        }
        __syncthreads();
        float d = 0.f;
        #pragma unroll 16
        for (int c = 0; c < 64; c++) d += qs[j][c] * cum[j][c];
        invd[(size_t)bh * TT + t0 + j] = 1.f / (d + 1e-6f);
        __syncthreads();
    }
}

// ---------------------------------------------------------------------------
// Single-phase causal attention: S = QK^T (tf32) -> write att = S*inv,
// O += tf32(S) @ V; upper-triangle tiles zero-filled.
// ---------------------------------------------------------------------------
#define ALD 72
#define ATTN_SMEM ((4*64*ALD + 64) * 4)

__global__ __launch_bounds__(256) void attn_tc(
    const float* __restrict__ qf, const float* __restrict__ kf,
    const float* __restrict__ vg, const float* __restrict__ invd,
    float* __restrict__ o, float* __restrict__ att)
{
    extern __shared__ float sm[];
    float (*Qs)[ALD] = (float(*)[ALD])(sm);
    float (*Ks)[ALD] = (float(*)[ALD])(sm + 64 * ALD);
    float (*Vs)[ALD] = (float(*)[ALD])(sm + 2 * 64 * ALD);
    float (*Ss)[ALD] = (float(*)[ALD])(sm + 3 * 64 * ALD);
    float* inv_s     = sm + 4 * 64 * ALD;

    const int tid = threadIdx.x;
    const int wid = tid >> 5;
    const int wr = wid >> 1, wc = wid & 1;
    const int rt = blockIdx.x, h = blockIdx.y, b = blockIdx.z;
    const int t0 = rt * 64;
    const size_t attBase = ((size_t)(b * HH + h)) * TT * TT;

    for (int e = tid; e < 64 * 64; e += 256) {
        int r = e >> 6, c = e & 63;
        Qs[r][c] = wmma::__float_to_tf32(
            qf[((size_t)(b * TT + t0 + r)) * PROJ + h * DK + c]);
    }
    if (tid < 64) inv_s[tid] = invd[((size_t)(b * HH + h)) * TT + t0 + tid];

    wmma::fragment<wmma::accumulator, 16, 16, 8, float> acc_o[2];
    wmma::fill_fragment(acc_o[0], 0.f);
    wmma::fill_fragment(acc_o[1], 0.f);

    for (int jt = 0; jt <= rt; jt++) {
        const int s0 = jt * 64;
        for (int e = tid; e < 64 * 64; e += 256) {
            int r = e >> 6, c = e & 63;
            size_t gi = ((size_t)(b * TT + s0 + r)) * PROJ + h * DK + c;
            Ks[r][c] = wmma::__float_to_tf32(kf[gi]);
            Vs[r][c] = wmma::__float_to_tf32(vg[gi]);
        }
        __syncthreads();

        wmma::fragment<wmma::accumulator, 16, 16, 8, float> acc_s[2];
        wmma::fill_fragment(acc_s[0], 0.f);
        wmma::fill_fragment(acc_s[1], 0.f);
        #pragma unroll
        for (int kk = 0; kk < 64; kk += 8) {
            wmma::fragment<wmma::matrix_a, 16, 16, 8, wmma::precision::tf32, wmma::row_major> af;
            wmma::fragment<wmma::matrix_b, 16, 16, 8, wmma::precision::tf32, wmma::col_major> bf[2];
            wmma::load_matrix_sync(af, &Qs[wr * 16][kk], ALD);
            wmma::load_matrix_sync(bf[0], &Ks[wc * 32][kk], ALD);
            wmma::load_matrix_sync(bf[1], &Ks[wc * 32 + 16][kk], ALD);
            wmma::mma_sync(acc_s[0], af, bf[0], acc_s[0]);
            wmma::mma_sync(acc_s[1], af, bf[1], acc_s[1]);
        }
        wmma::store_matrix_sync(&Ss[wr * 16][wc * 32], acc_s[0], ALD, wmma::mem_row_major);
        wmma::store_matrix_sync(&Ss[wr * 16][wc * 32 + 16], acc_s[1], ALD, wmma::mem_row_major);
        __syncthreads();

        // att write + causal mask + tf32 convert for S@V
        const bool diag = (jt == rt);
        for (int e = tid; e < 64 * 16; e += 256) {
            int r = e >> 4, c = (e & 15) * 4;
            float4 s = *(float4*)&Ss[r][c];
            if (diag) {
                if (c + 0 > r) s.x = 0.f;
                if (c + 1 > r) s.y = 0.f;
                if (c + 2 > r) s.z = 0.f;
                if (c + 3 > r) s.w = 0.f;
            }
            float iv = inv_s[r];
            float4 w = { s.x * iv, s.y * iv, s.z * iv, s.w * iv };
            *(float4*)(att + attBase + (size_t)(t0 + r) * TT + s0 + c) = w;
            Ss[r][c + 0] = wmma::__float_to_tf32(s.x);
            Ss[r][c + 1] = wmma::__float_to_tf32(s.y);
            Ss[r][c + 2] = wmma::__float_to_tf32(s.z);
            Ss[r][c + 3] = wmma::__float_to_tf32(s.w);
        }
        __syncthreads();

        #pragma unroll
        for (int kk = 0; kk < 64; kk += 8) {
            wmma::fragment<wmma::matrix_a, 16, 16, 8, wmma::precision::tf32, wmma::row_major> af;
            wmma::fragment<wmma::matrix_b, 16, 16, 8, wmma::precision::tf32, wmma::row_major> bf[2];
            wmma::load_matrix_sync(af, &Ss[wr * 16][kk], ALD);
            wmma::load_matrix_sync(bf[0], &Vs[kk][wc * 32], ALD);
            wmma::load_matrix_sync(bf[1], &Vs[kk][wc * 32 + 16], ALD);
            wmma::mma_sync(acc_o[0], af, bf[0], acc_o[0]);
            wmma::mma_sync(acc_o[1], af, bf[1], acc_o[1]);
        }
        __syncthreads();
    }

    // O = numer * inv
    wmma::store_matrix_sync(&Ss[wr * 16][wc * 32], acc_o[0], ALD, wmma::mem_row_major);
    wmma::store_matrix_sync(&Ss[wr * 16][wc * 32 + 16], acc_o[1], ALD, wmma::mem_row_major);
    __syncthreads();
    for (int e = tid; e < 64 * 16; e += 256) {
        int r = e >> 4, c = (e & 15) * 4;
        float4 s = *(float4*)&Ss[r][c];
        float iv = inv_s[r];
        float4 w = { s.x * iv, s.y * iv, s.z * iv, s.w * iv };
        *(float4*)(o + ((size_t)(b * TT + t0 + r)) * PROJ + h * DV + c) = w;
    }

    // zero-fill strictly-upper tiles
    const float4 z = { 0.f, 0.f, 0.f, 0.f };
    for (int jt = rt + 1; jt < TT / 64; jt++) {
        const int s0 = jt * 64;
        for (int e = tid; e < 64 * 16; e += 256) {
            int r = e >> 4, c = (e & 15) * 4;
            *(float4*)(att + attBase + (size_t)(t0 + r) * TT + s0 + c) = z;
        }
    }
}

// ---------------------------------------------------------------------------
extern "C" void kernel_launch(void* const* d_in, const int* in_sizes, int n_in,
                              void* d_out, int out_size)
{
    const float* query = (const float*)d_in[0];
    const float* key   = (const float*)d_in[1];
    const float* value = (const float*)d_in[2];
    const float* Wq    = (const float*)d_in[3];
    const float* Wk    = (const float*)d_in[4];
    const float* Wv    = (const float*)d_in[5];
    const float* Wg    = (const float*)d_in[6];
    const float* bg    = (const float*)d_in[7];
    const float* Wo    = (const float*)d_in[8];

    float* out = (float*)d_out;                 // [B,T,M]
    float* att = out + (size_t)NTOK * MM;       // [B,H,T,T]

    float *qf, *kf, *vg, *ov, *invd;
    cudaGetSymbolAddress((void**)&qf, g_qf);
    cudaGetSymbolAddress((void**)&kf, g_kf);
    cudaGetSymbolAddress((void**)&vg, g_v);
    cudaGetSymbolAddress((void**)&ov, g_o);
    cudaGetSymbolAddress((void**)&invd, g_inv);

    cudaFuncSetAttribute(gemm_db, cudaFuncAttributeMaxDynamicSharedMemorySize, GSMEM);
    cudaFuncSetAttribute(gemm_vg, cudaFuncAttributeMaxDynamicSharedMemorySize, VSMEM);
    cudaFuncSetAttribute(attn_tc, cudaFuncAttributeMaxDynamicSharedMemorySize, ATTN_SMEM);

    dim3 bb(256);

    // Q + K projections in one launch (grid.z selects)
    gemm_db<<<dim3(PROJ/64, NTOK/128, 2), bb, GSMEM>>>(
        query, Wq, qf, MODE_PHI, key, Wk, kf, MODE_PHI);

    // Fused V + gate projection
    gemm_vg<<<dim3(PROJ/64, NTOK/64), bb, VSMEM>>>(value, Wv, Wg, bg, vg);

    // Denominators (fp32 exact)
    denom_k<<<BB*HH, 64>>>(qf, kf, invd);

    // Attention: att_map + numer in one phase
    attn_tc<<<dim3(TT/64, HH, BB), bb, ATTN_SMEM>>>(qf, kf, vg, invd, ov, att);

    // Output projection
    gemm_db<<<dim3(MM/64, NTOK/128, 1), bb, GSMEM>>>(
        ov, Wo, out, MODE_RAW, ov, Wo, out, MODE_RAW);
}

// round 5
// speedup vs baseline: 1.4028x; 1.4028x over previous
#include <cuda_runtime.h>
#include <mma.h>
#include <math.h>
using namespace nvcuda;

#define BB 4
#define TT 1024
#define MM 512
#define HH 8
#define DK 64
#define DV 64
#define NTOK (BB*TT)          // 4096
#define PROJ (HH*DK)          // 512
#define NC   (TT/64)          // 16 chunks

__device__ float g_qf[NTOK*PROJ];
__device__ float g_kf[NTOK*PROJ];
__device__ float g_v [NTOK*PROJ];
__device__ float g_o [NTOK*PROJ];
__device__ float g_ktv  [BB*HH*NC*DK*DV];   // per-chunk K^T V
__device__ float g_state[BB*HH*NC*DK*DV];   // exclusive prefix of ktv (tf32-rounded)
__device__ float g_ksum [BB*HH*NC*DK];      // per-chunk column sums of kf
__device__ float g_inv  [BB*HH*TT];

enum { MODE_PHI = 0, MODE_RAW = 1 };

__device__ __forceinline__ void cp16(float* dst, const float* src) {
    unsigned d = (unsigned)__cvta_generic_to_shared(dst);
    asm volatile("cp.async.ca.shared.global [%0], [%1], 16;\n" :: "r"(d), "l"(src));
}
#define CP_COMMIT asm volatile("cp.async.commit_group;\n")
#define CP_WAIT1  asm volatile("cp.async.wait_group 1;\n")
#define CP_WAIT0  asm volatile("cp.async.wait_group 0;\n")

// ---------------------------------------------------------------------------
// Double-buffered TF32 GEMM: C = A[.,512] @ W[512,512] + epilogue.
// BM=128, BN=64, BK=32, 256 thr. grid.z selects problem. PHI output tf32-rounded.
// ---------------------------------------------------------------------------
#define LDA 40
#define LDB 72
#define LDC 72
#define GSMEM ((2*128*LDA + 2*32*LDB) * 4)

__global__ __launch_bounds__(256, 2) void gemm_db(
    const float* __restrict__ A0, const float* __restrict__ W0,
    float* __restrict__ C0, int mode0,
    const float* __restrict__ A1, const float* __restrict__ W1,
    float* __restrict__ C1, int mode1)
{
    extern __shared__ float sm[];
    float* Abuf[2] = { sm, sm + 128 * LDA };
    float* Bbuf[2] = { sm + 2 * 128 * LDA, sm + 2 * 128 * LDA + 32 * LDB };
    float (*Cs)[LDC] = (float(*)[LDC])sm;

    const float* A; const float* W; float* C; int mode;
    if (blockIdx.z == 0) { A = A0; W = W0; C = C0; mode = mode0; }
    else                 { A = A1; W = W1; C = C1; mode = mode1; }

    const int tid = threadIdx.x;
    const int wid = tid >> 5;
    const int wr = wid >> 1, wc = wid & 1;
    const int row0 = blockIdx.y * 128;
    const int col0 = blockIdx.x * 64;

    const int aR = tid >> 3, aC = (tid & 7) * 4;
    const int bR = tid >> 4, bC = (tid & 15) * 4;

    wmma::fragment<wmma::accumulator, 16, 16, 8, float> acc[2][2];
    #pragma unroll
    for (int i = 0; i < 2; i++)
        #pragma unroll
        for (int j = 0; j < 2; j++) wmma::fill_fragment(acc[i][j], 0.f);

    float4 pa[4], pb[2];
    #define LOAD_G(k0) { \
        _Pragma("unroll") \
        for (int p = 0; p < 4; p++) \
            pa[p] = *(const float4*)(A + (size_t)(row0 + aR + p * 32) * MM + (k0) + aC); \
        _Pragma("unroll") \
        for (int p = 0; p < 2; p++) \
            pb[p] = *(const float4*)(W + (size_t)((k0) + bR + p * 16) * PROJ + col0 + bC); }
    #define STORE_S(buf) { \
        float* As_ = Abuf[buf]; float* Bs_ = Bbuf[buf]; \
        _Pragma("unroll") \
        for (int p = 0; p < 4; p++) { \
            float* d = As_ + (aR + p * 32) * LDA + aC; \
            d[0] = wmma::__float_to_tf32(pa[p].x); d[1] = wmma::__float_to_tf32(pa[p].y); \
            d[2] = wmma::__float_to_tf32(pa[p].z); d[3] = wmma::__float_to_tf32(pa[p].w); } \
        _Pragma("unroll") \
        for (int p = 0; p < 2; p++) { \
            float* d = Bs_ + (bR + p * 16) * LDB + bC; \
            d[0] = wmma::__float_to_tf32(pb[p].x); d[1] = wmma::__float_to_tf32(pb[p].y); \
            d[2] = wmma::__float_to_tf32(pb[p].z); d[3] = wmma::__float_to_tf32(pb[p].w); } }

    LOAD_G(0); STORE_S(0); __syncthreads();
    int buf = 0;
    const int NTILE = MM / 32;
    for (int t = 0; t < NTILE; t++) {
        if (t + 1 < NTILE) LOAD_G((t + 1) * 32);
        float* As_ = Abuf[buf]; float* Bs_ = Bbuf[buf];
        #pragma unroll
        for (int kk = 0; kk < 32; kk += 8) {
            wmma::fragment<wmma::matrix_a, 16, 16, 8, wmma::precision::tf32, wmma::row_major> af[2];
            wmma::fragment<wmma::matrix_b, 16, 16, 8, wmma::precision::tf32, wmma::row_major> bf[2];
            #pragma unroll
            for (int i = 0; i < 2; i++)
                wmma::load_matrix_sync(af[i], As_ + (wr * 32 + i * 16) * LDA + kk, LDA);
            #pragma unroll
            for (int j = 0; j < 2; j++)
                wmma::load_matrix_sync(bf[j], Bs_ + kk * LDB + wc * 32 + j * 16, LDB);
            #pragma unroll
            for (int i = 0; i < 2; i++)
                #pragma unroll
                for (int j = 0; j < 2; j++)
                    wmma::mma_sync(acc[i][j], af[i], bf[j], acc[i][j]);
        }
        if (t + 1 < NTILE) STORE_S(buf ^ 1);
        __syncthreads();
        buf ^= 1;
    }

    #pragma unroll
    for (int i = 0; i < 2; i++)
        #pragma unroll
        for (int j = 0; j < 2; j++)
            wmma::store_matrix_sync(&Cs[wr * 32 + i * 16][wc * 32 + j * 16],
                                    acc[i][j], LDC, wmma::mem_row_major);
    __syncthreads();

    for (int e = tid; e < 128 * 16; e += 256) {
        int r = e >> 4, c = (e & 15) * 4;
        float4 v = *(float4*)&Cs[r][c];
        if (mode == MODE_PHI) {
            v.x = wmma::__float_to_tf32((v.x > 0.f) ? v.x + 1.f : expf(v.x));
            v.y = wmma::__float_to_tf32((v.y > 0.f) ? v.y + 1.f : expf(v.y));
            v.z = wmma::__float_to_tf32((v.z > 0.f) ? v.z + 1.f : expf(v.z));
            v.w = wmma::__float_to_tf32((v.w > 0.f) ? v.w + 1.f : expf(v.w));
        }
        *(float4*)(C + (size_t)(row0 + r) * PROJ + col0 + c) = v;
    }
    #undef LOAD_G
    #undef STORE_S
}

// ---------------------------------------------------------------------------
// Fused V + gate projection: vg = tf32((value@Wv) * 2*sigmoid(value@Wg + bg)).
// ---------------------------------------------------------------------------
#define VSMEM ((2*(64*LDA + 2*32*LDB)) * 4)

__global__ __launch_bounds__(256, 2) void gemm_vg(
    const float* __restrict__ A, const float* __restrict__ Wv,
    const float* __restrict__ Wg, const float* __restrict__ bg,
    float* __restrict__ C)
{
    extern __shared__ float sm[];
    const int HB = 64 * LDA + 2 * 32 * LDB;
    float* Abuf[2] = { sm, sm + HB };
    float* Vbuf[2] = { sm + 64 * LDA, sm + HB + 64 * LDA };
    float* Gbuf[2] = { sm + 64 * LDA + 32 * LDB, sm + HB + 64 * LDA + 32 * LDB };
    float (*Csv)[LDC] = (float(*)[LDC])sm;
    float (*Csg)[LDC] = (float(*)[LDC])(sm + 64 * LDC);

    const int tid = threadIdx.x;
    const int wid = tid >> 5;
    const int wr = wid >> 1, wc = wid & 1;
    const int row0 = blockIdx.y * 64;
    const int col0 = blockIdx.x * 64;

    const int aR = tid >> 3, aC = (tid & 7) * 4;
    const int bR = tid >> 4, bC = (tid & 15) * 4;

    wmma::fragment<wmma::accumulator, 16, 16, 8, float> accv[2], accg[2];
    #pragma unroll
    for (int j = 0; j < 2; j++) { wmma::fill_fragment(accv[j], 0.f); wmma::fill_fragment(accg[j], 0.f); }

    float4 pa[2], pv[2], pg[2];
    #define VG_LOAD(k0) { \
        _Pragma("unroll") \
        for (int p = 0; p < 2; p++) { \
            pa[p] = *(const float4*)(A  + (size_t)(row0 + aR + p * 32) * MM + (k0) + aC); \
            pv[p] = *(const float4*)(Wv + (size_t)((k0) + bR + p * 16) * PROJ + col0 + bC); \
            pg[p] = *(const float4*)(Wg + (size_t)((k0) + bR + p * 16) * PROJ + col0 + bC); } }
    #define VG_STORE(buf) { \
        _Pragma("unroll") \
        for (int p = 0; p < 2; p++) { \
            float* d = Abuf[buf] + (aR + p * 32) * LDA + aC; \
            d[0]=wmma::__float_to_tf32(pa[p].x); d[1]=wmma::__float_to_tf32(pa[p].y); \
            d[2]=wmma::__float_to_tf32(pa[p].z); d[3]=wmma::__float_to_tf32(pa[p].w); \
            float* dv = Vbuf[buf] + (bR + p * 16) * LDB + bC; \
            dv[0]=wmma::__float_to_tf32(pv[p].x); dv[1]=wmma::__float_to_tf32(pv[p].y); \
            dv[2]=wmma::__float_to_tf32(pv[p].z); dv[3]=wmma::__float_to_tf32(pv[p].w); \
            float* dg = Gbuf[buf] + (bR + p * 16) * LDB + bC; \
            dg[0]=wmma::__float_to_tf32(pg[p].x); dg[1]=wmma::__float_to_tf32(pg[p].y); \
            dg[2]=wmma::__float_to_tf32(pg[p].z); dg[3]=wmma::__float_to_tf32(pg[p].w); } }

    VG_LOAD(0); VG_STORE(0); __syncthreads();
    int buf = 0;
    const int NTILE = MM / 32;
    for (int t = 0; t < NTILE; t++) {
        if (t + 1 < NTILE) VG_LOAD((t + 1) * 32);
        float* As_ = Abuf[buf];
        #pragma unroll
        for (int kk = 0; kk < 32; kk += 8) {
            wmma::fragment<wmma::matrix_a, 16, 16, 8, wmma::precision::tf32, wmma::row_major> af;
            wmma::fragment<wmma::matrix_b, 16, 16, 8, wmma::precision::tf32, wmma::row_major> bfv[2], bfg[2];
            wmma::load_matrix_sync(af, As_ + (wr * 16) * LDA + kk, LDA);
            #pragma unroll
            for (int j = 0; j < 2; j++) {
                wmma::load_matrix_sync(bfv[j], Vbuf[buf] + kk * LDB + wc * 32 + j * 16, LDB);
                wmma::load_matrix_sync(bfg[j], Gbuf[buf] + kk * LDB + wc * 32 + j * 16, LDB);
            }
            #pragma unroll
            for (int j = 0; j < 2; j++) {
                wmma::mma_sync(accv[j], af, bfv[j], accv[j]);
                wmma::mma_sync(accg[j], af, bfg[j], accg[j]);
            }
        }
        if (t + 1 < NTILE) VG_STORE(buf ^ 1);
        __syncthreads();
        buf ^= 1;
    }

    #pragma unroll
    for (int j = 0; j < 2; j++) {
        wmma::store_matrix_sync(&Csv[wr * 16][wc * 32 + j * 16], accv[j], LDC, wmma::mem_row_major);
        wmma::store_matrix_sync(&Csg[wr * 16][wc * 32 + j * 16], accg[j], LDC, wmma::mem_row_major);
    }
    __syncthreads();

    for (int e = tid; e < 64 * 16; e += 256) {
        int r = e >> 4, c = (e & 15) * 4;
        float4 v = *(float4*)&Csv[r][c];
        float4 g = *(float4*)&Csg[r][c];
        v.x = wmma::__float_to_tf32(v.x * (2.f / (1.f + expf(-(g.x + bg[col0 + c + 0])))));
        v.y = wmma::__float_to_tf32(v.y * (2.f / (1.f + expf(-(g.y + bg[col0 + c + 1])))));
        v.z = wmma::__float_to_tf32(v.z * (2.f / (1.f + expf(-(g.z + bg[col0 + c + 2])))));
        v.w = wmma::__float_to_tf32(v.w * (2.f / (1.f + expf(-(g.w + bg[col0 + c + 3])))));
        *(float4*)(C + (size_t)(row0 + r) * PROJ + col0 + c) = v;
    }
    #undef VG_LOAD
    #undef VG_STORE
}

// ---------------------------------------------------------------------------
// Per-chunk K^T V (64x64) + per-chunk k column sums. grid (NC, H, B).
// ---------------------------------------------------------------------------
#define ALD 72

__global__ __launch_bounds__(256) void ktv_k(
    const float* __restrict__ kf, const float* __restrict__ vg,
    float* __restrict__ ktv, float* __restrict__ ksum)
{
    __shared__ float KT[64 * ALD];   // [kdim][t]
    __shared__ float Vc[64 * ALD];   // [t][v]
    const int c = blockIdx.x, h = blockIdx.y, b = blockIdx.z;
    const int tid = threadIdx.x;
    const int wid = tid >> 5, wr = wid >> 1, wc = wid & 1;
    const int t0 = c * 64;

    for (int e = tid; e < 4096; e += 256) {
        int t = e >> 6, kd = e & 63;
        KT[kd * ALD + t] = kf[((size_t)(b * TT + t0 + t)) * PROJ + h * DK + kd];
    }
    for (int e = tid; e < 64 * 16; e += 256) {
        int t = e >> 4, c4 = (e & 15) * 4;
        *(float4*)(Vc + t * ALD + c4) =
            *(const float4*)(vg + ((size_t)(b * TT + t0 + t)) * PROJ + h * DV + c4);
    }
    __syncthreads();

    if (tid < 64) {
        float s = 0.f;
        #pragma unroll 8
        for (int t = 0; t < 64; t++) s += KT[tid * ALD + t];
        ksum[(((size_t)(b * HH + h)) * NC + c) * DK + tid] = s;
    }

    wmma::fragment<wmma::accumulator, 16, 16, 8, float> acc[2];
    wmma::fill_fragment(acc[0], 0.f);
    wmma::fill_fragment(acc[1], 0.f);
    #pragma unroll
    for (int kk = 0; kk < 64; kk += 8) {
        wmma::fragment<wmma::matrix_a, 16, 16, 8, wmma::precision::tf32, wmma::row_major> af;
        wmma::fragment<wmma::matrix_b, 16, 16, 8, wmma::precision::tf32, wmma::row_major> bf[2];
        wmma::load_matrix_sync(af, KT + (wr * 16) * ALD + kk, ALD);
        wmma::load_matrix_sync(bf[0], Vc + kk * ALD + wc * 32, ALD);
        wmma::load_matrix_sync(bf[1], Vc + kk * ALD + wc * 32 + 16, ALD);
        wmma::mma_sync(acc[0], af, bf[0], acc[0]);
        wmma::mma_sync(acc[1], af, bf[1], acc[1]);
    }
    float* dst = ktv + (((size_t)(b * HH + h)) * NC + c) * 4096;
    wmma::store_matrix_sync(dst + (wr * 16) * 64 + wc * 32, acc[0], 64, wmma::mem_row_major);
    wmma::store_matrix_sync(dst + (wr * 16) * 64 + wc * 32 + 16, acc[1], 64, wmma::mem_row_major);
}

// ---------------------------------------------------------------------------
// Exclusive prefix over chunks -> tf32-rounded state.
// ---------------------------------------------------------------------------
__global__ __launch_bounds__(256) void state_k(
    const float* __restrict__ ktv, float* __restrict__ st)
{
    const int gid = blockIdx.x * 256 + threadIdx.x;   // 0..131071
    const int bh = gid >> 12, e = gid & 4095;
    const size_t base = ((size_t)bh * NC) * 4096 + e;
    float run = 0.f;
    #pragma unroll
    for (int c = 0; c < NC; c++) {
        st[base + c * 4096] = wmma::__float_to_tf32(run);
        run += ktv[base + c * 4096];
    }
}

// ---------------------------------------------------------------------------
// inv[t] = 1/(qf[t] . cumsum(kf)[t] + eps). grid (NC, H, B), 256 thr.
// ---------------------------------------------------------------------------
#define DLD 68
__global__ __launch_bounds__(256) void inv_k(
    const float* __restrict__ qf, const float* __restrict__ kf,
    const float* __restrict__ ksum, float* __restrict__ invd)
{
    __shared__ float Qc[64 * DLD];
    __shared__ float Kc[64 * DLD];   // overwritten in place by cumsum
    __shared__ float base[64];
    const int tile = blockIdx.x, h = blockIdx.y, b = blockIdx.z;
    const int tid = threadIdx.x;
    const int bh = b * HH + h;
    const int t0 = tile * 64;

    if (tid < 64) {
        float s = 0.f;
        for (int c = 0; c < tile; c++) s += ksum[((size_t)bh * NC + c) * DK + tid];
        base[tid] = s;
    }
    for (int e = tid; e < 64 * 16; e += 256) {
        int r = e >> 4, c4 = (e & 15) * 4;
        size_t gi = ((size_t)(b * TT + t0 + r)) * PROJ + h * DK + c4;
        *(float4*)(Qc + r * DLD + c4) = *(const float4*)(qf + gi);
        *(float4*)(Kc + r * DLD + c4) = *(const float4*)(kf + gi);
    }
    __syncthreads();
    if (tid < 64) {
        float run = base[tid];
        #pragma unroll 8
        for (int r = 0; r < 64; r++) { run += Kc[r * DLD + tid]; Kc[r * DLD + tid] = run; }
    }
    __syncthreads();
    const int row = tid >> 2, seg = tid & 3;
    float d = 0.f;
    #pragma unroll
    for (int i = 0; i < 16; i++)
        d += Qc[row * DLD + seg * 16 + i] * Kc[row * DLD + seg * 16 + i];
    d += __shfl_xor_sync(0xffffffff, d, 1);
    d += __shfl_xor_sync(0xffffffff, d, 2);
    if (seg == 0) invd[(size_t)bh * TT + t0 + row] = 1.f / (d + 1e-6f);
}

// ---------------------------------------------------------------------------
// Attention: per pair (rt=p, rt=15-p). Q pre-scaled by inv.
// O = Q' @ State_prev + masked(S_diag) @ V; att = S (frag-direct off-diag).
// ---------------------------------------------------------------------------
#define ATTN_SMEM ((5*64*ALD + 64) * 4)

__global__ __launch_bounds__(256) void attn_tc(
    const float* __restrict__ qf, const float* __restrict__ kf,
    const float* __restrict__ vg, const float* __restrict__ st,
    const float* __restrict__ invd,
    float* __restrict__ o, float* __restrict__ att)
{
    extern __shared__ float sm[];
    float* Qs = sm;
    float* K0 = sm + 64 * ALD;
    float* K1 = sm + 2 * 64 * ALD;
    float* Vs = sm + 3 * 64 * ALD;   // state, then V
    float* Ss = sm + 4 * 64 * ALD;
    float* inv_s = sm + 5 * 64 * ALD;

    const int tid = threadIdx.x;
    const int wid = tid >> 5, wr = wid >> 1, wc = wid & 1;
    const int pr = blockIdx.x, h = blockIdx.y, b = blockIdx.z;
    const int bh = b * HH + h;
    const size_t attBase = (size_t)bh * TT * TT;

    for (int half = 0; half < 2; half++) {
        const int rt = half ? (NC - 1 - pr) : pr;
        const int t0 = rt * 64;

        // state -> Vs (group 1)
        {
            const float* sb = st + ((size_t)bh * NC + rt) * 4096;
            #pragma unroll
            for (int p = 0; p < 4; p++) {
                int idx = tid + p * 256; int r = idx >> 4, s4 = (idx & 15) * 4;
                cp16(Vs + r * ALD + s4, sb + r * 64 + s4);
            }
        }
        CP_COMMIT;
        if (tid < 64) inv_s[tid] = invd[(size_t)bh * TT + t0 + tid];
        __syncthreads();

        // Q load + inv-scale + tf32
        #pragma unroll
        for (int p = 0; p < 4; p++) {
            int idx = tid + p * 256; int r = idx >> 4, c4 = (idx & 15) * 4;
            float4 q = *(const float4*)(qf + ((size_t)(b * TT + t0 + r)) * PROJ + h * DK + c4);
            float iv = inv_s[r];
            Qs[r * ALD + c4 + 0] = wmma::__float_to_tf32(q.x * iv);
            Qs[r * ALD + c4 + 1] = wmma::__float_to_tf32(q.y * iv);
            Qs[r * ALD + c4 + 2] = wmma::__float_to_tf32(q.z * iv);
            Qs[r * ALD + c4 + 3] = wmma::__float_to_tf32(q.w * iv);
        }
        // K(0) prefetch (group 2)
        #pragma unroll
        for (int p = 0; p < 4; p++) {
            int idx = tid + p * 256; int r = idx >> 4, s4 = (idx & 15) * 4;
            cp16(K0 + r * ALD + s4, kf + ((size_t)(b * TT + r)) * PROJ + h * DK + s4);
        }
        CP_COMMIT;
        CP_WAIT1;          // state arrived (K0 may fly)
        __syncthreads();

        // acc_o = Q' @ State_prev
        wmma::fragment<wmma::accumulator, 16, 16, 8, float> acc_o[2];
        wmma::fill_fragment(acc_o[0], 0.f);
        wmma::fill_fragment(acc_o[1], 0.f);
        #pragma unroll
        for (int kk = 0; kk < 64; kk += 8) {
            wmma::fragment<wmma::matrix_a, 16, 16, 8, wmma::precision::tf32, wmma::row_major> af;
            wmma::fragment<wmma::matrix_b, 16, 16, 8, wmma::precision::tf32, wmma::row_major> bf[2];
            wmma::load_matrix_sync(af, Qs + (wr * 16) * ALD + kk, ALD);
            wmma::load_matrix_sync(bf[0], Vs + kk * ALD + wc * 32, ALD);
            wmma::load_matrix_sync(bf[1], Vs + kk * ALD + wc * 32 + 16, ALD);
            wmma::mma_sync(acc_o[0], af, bf[0], acc_o[0]);
            wmma::mma_sync(acc_o[1], af, bf[1], acc_o[1]);
        }
        __syncthreads();   // everyone done reading state before V overwrites Vs

        for (int jt = 0; jt <= rt; jt++) {
            // prefetch next K (or V at diagonal)
            if (jt < rt) {
                float* dst = (jt & 1) ? K0 : K1;
                const float* src = kf + ((size_t)(b * TT + (jt + 1) * 64)) * PROJ + h * DK;
                #pragma unroll
                for (int p = 0; p < 4; p++) {
                    int idx = tid + p * 256; int r = idx >> 4, s4 = (idx & 15) * 4;
                    cp16(dst + r * ALD + s4, src + (size_t)r * PROJ + s4);
                }
            } else {
                const float* src = vg + ((size_t)(b * TT + t0)) * PROJ + h * DV;
                #pragma unroll
                for (int p = 0; p < 4; p++) {
                    int idx = tid + p * 256; int r = idx >> 4, s4 = (idx & 15) * 4;
                    cp16(Vs + r * ALD + s4, src + (size_t)r * PROJ + s4);
                }
            }
            CP_COMMIT;
            CP_WAIT1;      // current K tile arrived
            __syncthreads();

            float* Kc = (jt & 1) ? K1 : K0;
            wmma::fragment<wmma::accumulator, 16, 16, 8, float> acc_s[2];
            wmma::fill_fragment(acc_s[0], 0.f);
            wmma::fill_fragment(acc_s[1], 0.f);
            #pragma unroll
            for (int kk = 0; kk < 64; kk += 8) {
                wmma::fragment<wmma::matrix_a, 16, 16, 8, wmma::precision::tf32, wmma::row_major> af;
                wmma::fragment<wmma::matrix_b, 16, 16, 8, wmma::precision::tf32, wmma::col_major> bf[2];
                wmma::load_matrix_sync(af, Qs + (wr * 16) * ALD + kk, ALD);
                wmma::load_matrix_sync(bf[0], Kc + (wc * 32) * ALD + kk, ALD);
                wmma::load_matrix_sync(bf[1], Kc + (wc * 32 + 16) * ALD + kk, ALD);
                wmma::mma_sync(acc_s[0], af, bf[0], acc_s[0]);
                wmma::mma_sync(acc_s[1], af, bf[1], acc_s[1]);
            }

            if (jt < rt) {
                // off-diagonal: S is already final att value — store frags direct
                float* ap = att + attBase + (size_t)(t0 + wr * 16) * TT + jt * 64 + wc * 32;
                wmma::store_matrix_sync(ap, acc_s[0], TT, wmma::mem_row_major);
                wmma::store_matrix_sync(ap + 16, acc_s[1], TT, wmma::mem_row_major);
                __syncthreads();   // free Kc for prefetch at jt+1
            } else {
                // diagonal: mask, att write, tf32 convert, S@V, O write
                wmma::store_matrix_sync(Ss + (wr * 16) * ALD + wc * 32, acc_s[0], ALD, wmma::mem_row_major);
                wmma::store_matrix_sync(Ss + (wr * 16) * ALD + wc * 32 + 16, acc_s[1], ALD, wmma::mem_row_major);
                CP_WAIT0;          // V arrived
                __syncthreads();
                for (int e = tid; e < 64 * 16; e += 256) {
                    int r = e >> 4, c4 = (e & 15) * 4;
                    float4 s = *(float4*)(Ss + r * ALD + c4);
                    if (c4 + 0 > r) s.x = 0.f;
                    if (c4 + 1 > r) s.y = 0.f;
                    if (c4 + 2 > r) s.z = 0.f;
                    if (c4 + 3 > r) s.w = 0.f;
                    *(float4*)(att + attBase + (size_t)(t0 + r) * TT + t0 + c4) = s;
                    Ss[r * ALD + c4 + 0] = wmma::__float_to_tf32(s.x);
                    Ss[r * ALD + c4 + 1] = wmma::__float_to_tf32(s.y);
                    Ss[r * ALD + c4 + 2] = wmma::__float_to_tf32(s.z);
                    Ss[r * ALD + c4 + 3] = wmma::__float_to_tf32(s.w);
                }
                __syncthreads();
                #pragma unroll
                for (int kk = 0; kk < 64; kk += 8) {
                    wmma::fragment<wmma::matrix_a, 16, 16, 8, wmma::precision::tf32, wmma::row_major> af;
                    wmma::fragment<wmma::matrix_b, 16, 16, 8, wmma::precision::tf32, wmma::row_major> bf[2];
                    wmma::load_matrix_sync(af, Ss + (wr * 16) * ALD + kk, ALD);
                    wmma::load_matrix_sync(bf[0], Vs + kk * ALD + wc * 32, ALD);
                    wmma::load_matrix_sync(bf[1], Vs + kk * ALD + wc * 32 + 16, ALD);
                    wmma::mma_sync(acc_o[0], af, bf[0], acc_o[0]);
                    wmma::mma_sync(acc_o[1], af, bf[1], acc_o[1]);
                }
                float* op = o + ((size_t)(b * TT + t0 + wr * 16)) * PROJ + h * DV + wc * 32;
                wmma::store_matrix_sync(op, acc_o[0], PROJ, wmma::mem_row_major);
                wmma::store_matrix_sync(op + 16, acc_o[1], PROJ, wmma::mem_row_major);
            }
        }

        // zero-fill strictly-upper tiles
        const float4 z = { 0.f, 0.f, 0.f, 0.f };
        for (int jt = rt + 1; jt < NC; jt++) {
            for (int e = tid; e < 64 * 16; e += 256) {
                int r = e >> 4, c4 = (e & 15) * 4;
                *(float4*)(att + attBase + (size_t)(t0 + r) * TT + jt * 64 + c4) = z;
            }
        }
        __syncthreads();   // smem reuse barrier for next half
    }
}

// ---------------------------------------------------------------------------
extern "C" void kernel_launch(void* const* d_in, const int* in_sizes, int n_in,
                              void* d_out, int out_size)
{
    const float* query = (const float*)d_in[0];
    const float* key   = (const float*)d_in[1];
    const float* value = (const float*)d_in[2];
    const float* Wq    = (const float*)d_in[3];
    const float* Wk    = (const float*)d_in[4];
    const float* Wv    = (const float*)d_in[5];
    const float* Wg    = (const float*)d_in[6];
    const float* bg    = (const float*)d_in[7];
    const float* Wo    = (const float*)d_in[8];

    float* out = (float*)d_out;                 // [B,T,M]
    float* att = out + (size_t)NTOK * MM;       // [B,H,T,T]

    float *qf, *kf, *vg, *ov, *ktv, *st, *ksum, *invd;
    cudaGetSymbolAddress((void**)&qf, g_qf);
    cudaGetSymbolAddress((void**)&kf, g_kf);
    cudaGetSymbolAddress((void**)&vg, g_v);
    cudaGetSymbolAddress((void**)&ov, g_o);
    cudaGetSymbolAddress((void**)&ktv, g_ktv);
    cudaGetSymbolAddress((void**)&st, g_state);
    cudaGetSymbolAddress((void**)&ksum, g_ksum);
    cudaGetSymbolAddress((void**)&invd, g_inv);

    cudaFuncSetAttribute(gemm_db, cudaFuncAttributeMaxDynamicSharedMemorySize, GSMEM);
    cudaFuncSetAttribute(gemm_vg, cudaFuncAttributeMaxDynamicSharedMemorySize, VSMEM);
    cudaFuncSetAttribute(attn_tc, cudaFuncAttributeMaxDynamicSharedMemorySize, ATTN_SMEM);

    dim3 bb(256);

    // Q + K projections (phi, tf32-rounded outputs)
    gemm_db<<<dim3(PROJ/64, NTOK/128, 2), bb, GSMEM>>>(
        query, Wq, qf, MODE_PHI, key, Wk, kf, MODE_PHI);

    // Fused V + gate projection (tf32-rounded)
    gemm_vg<<<dim3(PROJ/64, NTOK/64), bb, VSMEM>>>(value, Wv, Wg, bg, vg);

    // Per-chunk K^T V + k sums
    ktv_k<<<dim3(NC, HH, BB), bb>>>(kf, vg, ktv, ksum);

    // Exclusive state prefix
    state_k<<<dim3(BB*HH*TT*DK/ (256*16) * 16 / 16, 1, 1), bb>>>(ktv, st);  // 512 blocks

    // inv denominators
    inv_k<<<dim3(NC, HH, BB), bb>>>(qf, kf, ksum, invd);

    // Attention (paired row tiles)
    attn_tc<<<dim3(NC/2, HH, BB), bb, ATTN_SMEM>>>(qf, kf, vg, st, invd, ov, att);

    // Output projection
    gemm_db<<<dim3(MM/64, NTOK/128, 1), bb, GSMEM>>>(
        ov, Wo, out, MODE_RAW, ov, Wo, out, MODE_RAW);
}

// round 6
// speedup vs baseline: 1.5792x; 1.1258x over previous
#include <cuda_runtime.h>
#include <mma.h>
#include <math.h>
using namespace nvcuda;

#define BB 4
#define TT 1024
#define MM 512
#define HH 8
#define DK 64
#define DV 64
#define NTOK (BB*TT)          // 4096
#define PROJ (HH*DK)          // 512
#define NC   (TT/64)          // 16 chunks

enum { MODE_PHI = 0, MODE_RAW = 1 };

// Scratch (no cudaMalloc allowed)
__device__ float g_rq[NTOK*MM];
__device__ float g_rk[NTOK*MM];
__device__ float g_rv[NTOK*MM];
__device__ float g_w [5*MM*PROJ];           // rounded Wq,Wk,Wv,Wg,Wo
__device__ float g_qf[NTOK*PROJ];
__device__ float g_kf[NTOK*PROJ];
__device__ float g_v [NTOK*PROJ];
__device__ float g_gt[NTOK*PROJ];
__device__ float g_o [NTOK*PROJ];
__device__ float g_ktv  [BB*HH*NC*DK*DV];
__device__ float g_state[BB*HH*NC*DK*DV];
__device__ float g_ksum [BB*HH*NC*DK];
__device__ float g_inv  [BB*HH*TT];

__device__ __forceinline__ void cp16(float* dst, const float* src) {
    unsigned d = (unsigned)__cvta_generic_to_shared(dst);
    asm volatile("cp.async.ca.shared.global [%0], [%1], 16;\n" :: "r"(d), "l"(src));
}
#define CP_COMMIT asm volatile("cp.async.commit_group;\n")
#define CP_WAIT1  asm volatile("cp.async.wait_group 1;\n")
#define CP_WAIT0  asm volatile("cp.async.wait_group 0;\n")

// ---------------------------------------------------------------------------
// Pre-round inputs to tf32 (RNA) so GEMMs can cp.async raw bits.
// ---------------------------------------------------------------------------
__global__ __launch_bounds__(256) void preround3(
    const float* __restrict__ q, const float* __restrict__ k,
    const float* __restrict__ v,
    float* __restrict__ rq, float* __restrict__ rk, float* __restrict__ rv)
{
    const float* src = (blockIdx.z == 0) ? q : (blockIdx.z == 1) ? k : v;
    float*       dst = (blockIdx.z == 0) ? rq : (blockIdx.z == 1) ? rk : rv;
    int i = blockIdx.x * 256 + threadIdx.x;       // float4 index, 524288 total
    float4 x = ((const float4*)src)[i];
    x.x = wmma::__float_to_tf32(x.x); x.y = wmma::__float_to_tf32(x.y);
    x.z = wmma::__float_to_tf32(x.z); x.w = wmma::__float_to_tf32(x.w);
    ((float4*)dst)[i] = x;
}

struct WArgs { const float* in[5]; };
__global__ __launch_bounds__(256) void preround_w(WArgs wa, float* __restrict__ out)
{
    const float* src = wa.in[blockIdx.z];
    float* dst = out + (size_t)blockIdx.z * MM * PROJ;
    int i = blockIdx.x * 256 + threadIdx.x;       // float4 index, 65536 total
    float4 x = ((const float4*)src)[i];
    x.x = wmma::__float_to_tf32(x.x); x.y = wmma::__float_to_tf32(x.y);
    x.z = wmma::__float_to_tf32(x.z); x.w = wmma::__float_to_tf32(x.w);
    ((float4*)dst)[i] = x;
}

// ---------------------------------------------------------------------------
// Unified 3-stage cp.async TF32 GEMM: C[4096,512] = A[4096,512] @ W[512,512].
// BM=128, BN=128, BK=32, 256 thr, warp tile 32x64 (2x4 frags). grid.z batches.
// Inputs MUST be tf32-pre-rounded. PHI epilogue writes tf32-rounded phi(x).
// ---------------------------------------------------------------------------
#define AP 36
#define BP 132
#define STG (128*AP + 32*BP)               // 8832 floats / stage
#define GSM (3*STG*4)                      // 105984 B

struct GemmArgs { const float* A[4]; const float* W[4]; float* C[4]; int mode[4]; };

__global__ __launch_bounds__(256, 2) void gemm128(GemmArgs ga)
{
    extern __shared__ float sm[];
    const int z = blockIdx.z;
    const float* A = ga.A[z]; const float* W = ga.W[z];
    float* C = ga.C[z]; const int mode = ga.mode[z];

    const int tid = threadIdx.x;
    const int wid = tid >> 5, lane = tid & 31;
    const int wr = wid >> 1, wc = wid & 1;
    const int row0 = blockIdx.y * 128, col0 = blockIdx.x * 128;

    wmma::fragment<wmma::accumulator, 16, 16, 8, float> acc[2][4];
    #pragma unroll
    for (int i = 0; i < 2; i++)
        #pragma unroll
        for (int j = 0; j < 4; j++) wmma::fill_fragment(acc[i][j], 0.f);

    #define ISSUE(s, kt) { \
        float* As_ = sm + (s) * STG; \
        float* Bs_ = As_ + 128 * AP; \
        const float* Ag = A + (size_t)row0 * 512 + (kt) * 32; \
        const float* Wg_ = W + (size_t)((kt) * 32) * 512 + col0; \
        _Pragma("unroll") \
        for (int p = 0; p < 4; p++) { \
            int idx = tid + p * 256; \
            int r = idx >> 3, c4 = (idx & 7) * 4; \
            cp16(As_ + r * AP + c4, Ag + (size_t)r * 512 + c4); \
        } \
        _Pragma("unroll") \
        for (int p = 0; p < 4; p++) { \
            int idx = tid + p * 256; \
            int r = idx >> 5, c4 = (idx & 31) * 4; \
            cp16(Bs_ + r * BP + c4, Wg_ + (size_t)r * 512 + c4); \
        } \
        CP_COMMIT; }

    ISSUE(0, 0); ISSUE(1, 1);
    for (int t = 0; t < 16; t++) {
        if (t < 15) { CP_WAIT1; } else { CP_WAIT0; }
        __syncthreads();
        float* As_ = sm + (t % 3) * STG;
        float* Bs_ = As_ + 128 * AP;
        #pragma unroll
        for (int kk = 0; kk < 32; kk += 8) {
            wmma::fragment<wmma::matrix_a, 16, 16, 8, wmma::precision::tf32, wmma::row_major> af[2];
            wmma::fragment<wmma::matrix_b, 16, 16, 8, wmma::precision::tf32, wmma::row_major> bf[4];
            #pragma unroll
            for (int i = 0; i < 2; i++)
                wmma::load_matrix_sync(af[i], As_ + (wr * 32 + i * 16) * AP + kk, AP);
            #pragma unroll
            for (int j = 0; j < 4; j++)
                wmma::load_matrix_sync(bf[j], Bs_ + kk * BP + wc * 64 + j * 16, BP);
            #pragma unroll
            for (int i = 0; i < 2; i++)
                #pragma unroll
                for (int j = 0; j < 4; j++)
                    wmma::mma_sync(acc[i][j], af[i], bf[j], acc[i][j]);
        }
        if (t + 2 < 16) ISSUE((t + 2) % 3, t + 2);
    }
    __syncthreads();
    #undef ISSUE

    // Epilogue: per-warp strip (32x64, ld 68) in smem, coalesced writes.
    float* strip = sm + wid * (32 * 68);
    #pragma unroll
    for (int i = 0; i < 2; i++)
        #pragma unroll
        for (int j = 0; j < 4; j++)
            wmma::store_matrix_sync(strip + (i * 16) * 68 + j * 16, acc[i][j],
                                    68, wmma::mem_row_major);
    __syncwarp();
    #pragma unroll
    for (int i2 = 0; i2 < 16; i2++) {
        int e = lane + i2 * 32;
        int r = e >> 4, c4 = (e & 15) * 4;
        float4 v = *(float4*)(strip + r * 68 + c4);
        if (mode == MODE_PHI) {
            v.x = wmma::__float_to_tf32((v.x > 0.f) ? v.x + 1.f : expf(v.x));
            v.y = wmma::__float_to_tf32((v.y > 0.f) ? v.y + 1.f : expf(v.y));
            v.z = wmma::__float_to_tf32((v.z > 0.f) ? v.z + 1.f : expf(v.z));
            v.w = wmma::__float_to_tf32((v.w > 0.f) ? v.w + 1.f : expf(v.w));
        }
        *(float4*)(C + (size_t)(row0 + wr * 32 + r) * 512 + col0 + wc * 64 + c4) = v;
    }
}

// ---------------------------------------------------------------------------
// Gate: vg = tf32(v * 2*sigmoid(g + bg)), elementwise in-place on g_v.
// ---------------------------------------------------------------------------
__global__ __launch_bounds__(256) void gate_k(
    float* __restrict__ v, const float* __restrict__ g, const float* __restrict__ bg)
{
    const int n4 = NTOK * PROJ / 4;
    for (int i = blockIdx.x * 256 + threadIdx.x; i < n4; i += gridDim.x * 256) {
        float4 vv = ((float4*)v)[i];
        float4 gg = ((const float4*)g)[i];
        int col = (i * 4) & 511;
        vv.x = wmma::__float_to_tf32(vv.x * (2.f / (1.f + expf(-(gg.x + bg[col + 0])))));
        vv.y = wmma::__float_to_tf32(vv.y * (2.f / (1.f + expf(-(gg.y + bg[col + 1])))));
        vv.z = wmma::__float_to_tf32(vv.z * (2.f / (1.f + expf(-(gg.z + bg[col + 2])))));
        vv.w = wmma::__float_to_tf32(vv.w * (2.f / (1.f + expf(-(gg.w + bg[col + 3])))));
        ((float4*)v)[i] = vv;
    }
}

// ---------------------------------------------------------------------------
// Per-chunk K^T V (64x64) + per-chunk k column sums. grid (NC, H, B).
// ---------------------------------------------------------------------------
#define ALD 72

__global__ __launch_bounds__(256) void ktv_k(
    const float* __restrict__ kf, const float* __restrict__ vg,
    float* __restrict__ ktv, float* __restrict__ ksum)
{
    __shared__ float KT[64 * ALD];   // [kdim][t]
    __shared__ float Vc[64 * ALD];   // [t][v]
    const int c = blockIdx.x, h = blockIdx.y, b = blockIdx.z;
    const int tid = threadIdx.x;
    const int wid = tid >> 5, wr = wid >> 1, wc = wid & 1;
    const int t0 = c * 64;

    for (int e = tid; e < 4096; e += 256) {
        int t = e >> 6, kd = e & 63;
        KT[kd * ALD + t] = kf[((size_t)(b * TT + t0 + t)) * PROJ + h * DK + kd];
    }
    for (int e = tid; e < 64 * 16; e += 256) {
        int t = e >> 4, c4 = (e & 15) * 4;
        *(float4*)(Vc + t * ALD + c4) =
            *(const float4*)(vg + ((size_t)(b * TT + t0 + t)) * PROJ + h * DV + c4);
    }
    __syncthreads();

    if (tid < 64) {
        float s = 0.f;
        #pragma unroll 8
        for (int t = 0; t < 64; t++) s += KT[tid * ALD + t];
        ksum[(((size_t)(b * HH + h)) * NC + c) * DK + tid] = s;
    }

    wmma::fragment<wmma::accumulator, 16, 16, 8, float> acc[2];
    wmma::fill_fragment(acc[0], 0.f);
    wmma::fill_fragment(acc[1], 0.f);
    #pragma unroll
    for (int kk = 0; kk < 64; kk += 8) {
        wmma::fragment<wmma::matrix_a, 16, 16, 8, wmma::precision::tf32, wmma::row_major> af;
        wmma::fragment<wmma::matrix_b, 16, 16, 8, wmma::precision::tf32, wmma::row_major> bf[2];
        wmma::load_matrix_sync(af, KT + (wr * 16) * ALD + kk, ALD);
        wmma::load_matrix_sync(bf[0], Vc + kk * ALD + wc * 32, ALD);
        wmma::load_matrix_sync(bf[1], Vc + kk * ALD + wc * 32 + 16, ALD);
        wmma::mma_sync(acc[0], af, bf[0], acc[0]);
        wmma::mma_sync(acc[1], af, bf[1], acc[1]);
    }
    float* dst = ktv + (((size_t)(b * HH + h)) * NC + c) * 4096;
    wmma::store_matrix_sync(dst + (wr * 16) * 64 + wc * 32, acc[0], 64, wmma::mem_row_major);
    wmma::store_matrix_sync(dst + (wr * 16) * 64 + wc * 32 + 16, acc[1], 64, wmma::mem_row_major);
}

// ---------------------------------------------------------------------------
// Exclusive prefix over chunks -> tf32-rounded state.
// ---------------------------------------------------------------------------
__global__ __launch_bounds__(256) void state_k(
    const float* __restrict__ ktv, float* __restrict__ st)
{
    const int gid = blockIdx.x * 256 + threadIdx.x;   // 0..131071
    const int bh = gid >> 12, e = gid & 4095;
    const size_t base = ((size_t)bh * NC) * 4096 + e;
    float run = 0.f;
    #pragma unroll
    for (int c = 0; c < NC; c++) {
        st[base + c * 4096] = wmma::__float_to_tf32(run);
        run += ktv[base + c * 4096];
    }
}

// ---------------------------------------------------------------------------
// inv[t] = 1/(qf[t] . cumsum(kf)[t] + eps). grid (NC, H, B), 256 thr.
// ---------------------------------------------------------------------------
#define DLD 68
__global__ __launch_bounds__(256) void inv_k(
    const float* __restrict__ qf, const float* __restrict__ kf,
    const float* __restrict__ ksum, float* __restrict__ invd)
{
    __shared__ float Qc[64 * DLD];
    __shared__ float Kc[64 * DLD];
    __shared__ float base[64];
    const int tile = blockIdx.x, h = blockIdx.y, b = blockIdx.z;
    const int tid = threadIdx.x;
    const int bh = b * HH + h;
    const int t0 = tile * 64;

    if (tid < 64) {
        float s = 0.f;
        for (int c = 0; c < tile; c++) s += ksum[((size_t)bh * NC + c) * DK + tid];
        base[tid] = s;
    }
    for (int e = tid; e < 64 * 16; e += 256) {
        int r = e >> 4, c4 = (e & 15) * 4;
        size_t gi = ((size_t)(b * TT + t0 + r)) * PROJ + h * DK + c4;
        *(float4*)(Qc + r * DLD + c4) = *(const float4*)(qf + gi);
        *(float4*)(Kc + r * DLD + c4) = *(const float4*)(kf + gi);
    }
    __syncthreads();
    if (tid < 64) {
        float run = base[tid];
        #pragma unroll 8
        for (int r = 0; r < 64; r++) { run += Kc[r * DLD + tid]; Kc[r * DLD + tid] = run; }
    }
    __syncthreads();
    const int row = tid >> 2, seg = tid & 3;
    float d = 0.f;
    #pragma unroll
    for (int i = 0; i < 16; i++)
        d += Qc[row * DLD + seg * 16 + i] * Kc[row * DLD + seg * 16 + i];
    d += __shfl_xor_sync(0xffffffff, d, 1);
    d += __shfl_xor_sync(0xffffffff, d, 2);
    if (seg == 0) invd[(size_t)bh * TT + t0 + row] = 1.f / (d + 1e-6f);
}

// ---------------------------------------------------------------------------
// Attention: per pair (rt=p, rt=15-p). Q pre-scaled by inv.
// O = Q' @ State_prev + masked(S_diag) @ V; att = S (frag-direct off-diag).
// O written tf32-rounded so the out-proj can cp.async it.
// ---------------------------------------------------------------------------
#define ATTN_SMEM ((5*64*ALD + 64) * 4)

__global__ __launch_bounds__(256) void attn_tc(
    const float* __restrict__ qf, const float* __restrict__ kf,
    const float* __restrict__ vg, const float* __restrict__ st,
    const float* __restrict__ invd,
    float* __restrict__ o, float* __restrict__ att)
{
    extern __shared__ float sm[];
    float* Qs = sm;
    float* K0 = sm + 64 * ALD;
    float* K1 = sm + 2 * 64 * ALD;
    float* Vs = sm + 3 * 64 * ALD;   // state, then V
    float* Ss = sm + 4 * 64 * ALD;
    float* inv_s = sm + 5 * 64 * ALD;

    const int tid = threadIdx.x;
    const int wid = tid >> 5, wr = wid >> 1, wc = wid & 1;
    const int pr = blockIdx.x, h = blockIdx.y, b = blockIdx.z;
    const int bh = b * HH + h;
    const size_t attBase = (size_t)bh * TT * TT;

    for (int half = 0; half < 2; half++) {
        const int rt = half ? (NC - 1 - pr) : pr;
        const int t0 = rt * 64;

        // state -> Vs (group 1)
        {
            const float* sb = st + ((size_t)bh * NC + rt) * 4096;
            #pragma unroll
            for (int p = 0; p < 4; p++) {
                int idx = tid + p * 256; int r = idx >> 4, s4 = (idx & 15) * 4;
                cp16(Vs + r * ALD + s4, sb + r * 64 + s4);
            }
        }
        CP_COMMIT;
        if (tid < 64) inv_s[tid] = invd[(size_t)bh * TT + t0 + tid];
        __syncthreads();

        // Q load + inv-scale + tf32
        #pragma unroll
        for (int p = 0; p < 4; p++) {
            int idx = tid + p * 256; int r = idx >> 4, c4 = (idx & 15) * 4;
            float4 q = *(const float4*)(qf + ((size_t)(b * TT + t0 + r)) * PROJ + h * DK + c4);
            float iv = inv_s[r];
            Qs[r * ALD + c4 + 0] = wmma::__float_to_tf32(q.x * iv);
            Qs[r * ALD + c4 + 1] = wmma::__float_to_tf32(q.y * iv);
            Qs[r * ALD + c4 + 2] = wmma::__float_to_tf32(q.z * iv);
            Qs[r * ALD + c4 + 3] = wmma::__float_to_tf32(q.w * iv);
        }
        // K(0) prefetch (group 2)
        #pragma unroll
        for (int p = 0; p < 4; p++) {
            int idx = tid + p * 256; int r = idx >> 4, s4 = (idx & 15) * 4;
            cp16(K0 + r * ALD + s4, kf + ((size_t)(b * TT + r)) * PROJ + h * DK + s4);
        }
        CP_COMMIT;
        CP_WAIT1;          // state arrived (K0 may fly)
        __syncthreads();

        // acc_o = Q' @ State_prev
        wmma::fragment<wmma::accumulator, 16, 16, 8, float> acc_o[2];
        wmma::fill_fragment(acc_o[0], 0.f);
        wmma::fill_fragment(acc_o[1], 0.f);
        #pragma unroll
        for (int kk = 0; kk < 64; kk += 8) {
            wmma::fragment<wmma::matrix_a, 16, 16, 8, wmma::precision::tf32, wmma::row_major> af;
            wmma::fragment<wmma::matrix_b, 16, 16, 8, wmma::precision::tf32, wmma::row_major> bf[2];
            wmma::load_matrix_sync(af, Qs + (wr * 16) * ALD + kk, ALD);
            wmma::load_matrix_sync(bf[0], Vs + kk * ALD + wc * 32, ALD);
            wmma::load_matrix_sync(bf[1], Vs + kk * ALD + wc * 32 + 16, ALD);
            wmma::mma_sync(acc_o[0], af, bf[0], acc_o[0]);
            wmma::mma_sync(acc_o[1], af, bf[1], acc_o[1]);
        }
        __syncthreads();   // state reads done before V overwrites Vs

        for (int jt = 0; jt <= rt; jt++) {
            if (jt < rt) {
                float* dst = (jt & 1) ? K0 : K1;
                const float* src = kf + ((size_t)(b * TT + (jt + 1) * 64)) * PROJ + h * DK;
                #pragma unroll
                for (int p = 0; p < 4; p++) {
                    int idx = tid + p * 256; int r = idx >> 4, s4 = (idx & 15) * 4;
                    cp16(dst + r * ALD + s4, src + (size_t)r * PROJ + s4);
                }
            } else {
                const float* src = vg + ((size_t)(b * TT + t0)) * PROJ + h * DV;
                #pragma unroll
                for (int p = 0; p < 4; p++) {
                    int idx = tid + p * 256; int r = idx >> 4, s4 = (idx & 15) * 4;
                    cp16(Vs + r * ALD + s4, src + (size_t)r * PROJ + s4);
                }
            }
            CP_COMMIT;
            CP_WAIT1;      // current K tile arrived
            __syncthreads();

            float* Kc = (jt & 1) ? K1 : K0;
            wmma::fragment<wmma::accumulator, 16, 16, 8, float> acc_s[2];
            wmma::fill_fragment(acc_s[0], 0.f);
            wmma::fill_fragment(acc_s[1], 0.f);
            #pragma unroll
            for (int kk = 0; kk < 64; kk += 8) {
                wmma::fragment<wmma::matrix_a, 16, 16, 8, wmma::precision::tf32, wmma::row_major> af;
                wmma::fragment<wmma::matrix_b, 16, 16, 8, wmma::precision::tf32, wmma::col_major> bf[2];
                wmma::load_matrix_sync(af, Qs + (wr * 16) * ALD + kk, ALD);
                wmma::load_matrix_sync(bf[0], Kc + (wc * 32) * ALD + kk, ALD);
                wmma::load_matrix_sync(bf[1], Kc + (wc * 32 + 16) * ALD + kk, ALD);
                wmma::mma_sync(acc_s[0], af, bf[0], acc_s[0]);
                wmma::mma_sync(acc_s[1], af, bf[1], acc_s[1]);
            }

            if (jt < rt) {
                // off-diagonal: S is the final att value — store frags direct
                float* ap = att + attBase + (size_t)(t0 + wr * 16) * TT + jt * 64 + wc * 32;
                wmma::store_matrix_sync(ap, acc_s[0], TT, wmma::mem_row_major);
                wmma::store_matrix_sync(ap + 16, acc_s[1], TT, wmma::mem_row_major);
                __syncthreads();   // free Kc for prefetch at jt+1
            } else {
                // diagonal: mask, att write, tf32 convert, S@V, rounded O write
                wmma::store_matrix_sync(Ss + (wr * 16) * ALD + wc * 32, acc_s[0], ALD, wmma::mem_row_major);
                wmma::store_matrix_sync(Ss + (wr * 16) * ALD + wc * 32 + 16, acc_s[1], ALD, wmma::mem_row_major);
                CP_WAIT0;          // V arrived
                __syncthreads();
                for (int e = tid; e < 64 * 16; e += 256) {
                    int r = e >> 4, c4 = (e & 15) * 4;
                    float4 s = *(float4*)(Ss + r * ALD + c4);
                    if (c4 + 0 > r) s.x = 0.f;
                    if (c4 + 1 > r) s.y = 0.f;
                    if (c4 + 2 > r) s.z = 0.f;
                    if (c4 + 3 > r) s.w = 0.f;
                    *(float4*)(att + attBase + (size_t)(t0 + r) * TT + t0 + c4) = s;
                    Ss[r * ALD + c4 + 0] = wmma::__float_to_tf32(s.x);
                    Ss[r * ALD + c4 + 1] = wmma::__float_to_tf32(s.y);
                    Ss[r * ALD + c4 + 2] = wmma::__float_to_tf32(s.z);
                    Ss[r * ALD + c4 + 3] = wmma::__float_to_tf32(s.w);
                }
                __syncthreads();
                #pragma unroll
                for (int kk = 0; kk < 64; kk += 8) {
                    wmma::fragment<wmma::matrix_a, 16, 16, 8, wmma::precision::tf32, wmma::row_major> af;
                    wmma::fragment<wmma::matrix_b, 16, 16, 8, wmma::precision::tf32, wmma::row_major> bf[2];
                    wmma::load_matrix_sync(af, Ss + (wr * 16) * ALD + kk, ALD);
                    wmma::load_matrix_sync(bf[0], Vs + kk * ALD + wc * 32, ALD);
                    wmma::load_matrix_sync(bf[1], Vs + kk * ALD + wc * 32 + 16, ALD);
                    wmma::mma_sync(acc_o[0], af, bf[0], acc_o[0]);
                    wmma::mma_sync(acc_o[1], af, bf[1], acc_o[1]);
                }
                // rounded O via smem staging (Ss free after mma; sync first)
                __syncthreads();
                wmma::store_matrix_sync(Ss + (wr * 16) * ALD + wc * 32, acc_o[0], ALD, wmma::mem_row_major);
                wmma::store_matrix_sync(Ss + (wr * 16) * ALD + wc * 32 + 16, acc_o[1], ALD, wmma::mem_row_major);
                __syncthreads();
                for (int e = tid; e < 64 * 16; e += 256) {
                    int r = e >> 4, c4 = (e & 15) * 4;
                    float4 s = *(float4*)(Ss + r * ALD + c4);
                    s.x = wmma::__float_to_tf32(s.x);
                    s.y = wmma::__float_to_tf32(s.y);
                    s.z = wmma::__float_to_tf32(s.z);
                    s.w = wmma::__float_to_tf32(s.w);
                    *(float4*)(o + ((size_t)(b * TT + t0 + r)) * PROJ + h * DV + c4) = s;
                }
            }
        }

        // zero-fill strictly-upper tiles
        const float4 z = { 0.f, 0.f, 0.f, 0.f };
        for (int jt = rt + 1; jt < NC; jt++) {
            for (int e = tid; e < 64 * 16; e += 256) {
                int r = e >> 4, c4 = (e & 15) * 4;
                *(float4*)(att + attBase + (size_t)(t0 + r) * TT + jt * 64 + c4) = z;
            }
        }
        __syncthreads();   // smem reuse barrier for next half
    }
}

// ---------------------------------------------------------------------------
extern "C" void kernel_launch(void* const* d_in, const int* in_sizes, int n_in,
                              void* d_out, int out_size)
{
    const float* query = (const float*)d_in[0];
    const float* key   = (const float*)d_in[1];
    const float* value = (const float*)d_in[2];
    const float* Wq    = (const float*)d_in[3];
    const float* Wk    = (const float*)d_in[4];
    const float* Wv    = (const float*)d_in[5];
    const float* Wg    = (const float*)d_in[6];
    const float* bg    = (const float*)d_in[7];
    const float* Wo    = (const float*)d_in[8];

    float* out = (float*)d_out;                 // [B,T,M]
    float* att = out + (size_t)NTOK * MM;       // [B,H,T,T]

    float *rq, *rk, *rv, *w, *qf, *kf, *vg, *gt, *ov, *ktv, *st, *ksum, *invd;
    cudaGetSymbolAddress((void**)&rq, g_rq);
    cudaGetSymbolAddress((void**)&rk, g_rk);
    cudaGetSymbolAddress((void**)&rv, g_rv);
    cudaGetSymbolAddress((void**)&w,  g_w);
    cudaGetSymbolAddress((void**)&qf, g_qf);
    cudaGetSymbolAddress((void**)&kf, g_kf);
    cudaGetSymbolAddress((void**)&vg, g_v);
    cudaGetSymbolAddress((void**)&gt, g_gt);
    cudaGetSymbolAddress((void**)&ov, g_o);
    cudaGetSymbolAddress((void**)&ktv, g_ktv);
    cudaGetSymbolAddress((void**)&st, g_state);
    cudaGetSymbolAddress((void**)&ksum, g_ksum);
    cudaGetSymbolAddress((void**)&invd, g_inv);

    cudaFuncSetAttribute(gemm128, cudaFuncAttributeMaxDynamicSharedMemorySize, GSM);
    cudaFuncSetAttribute(attn_tc, cudaFuncAttributeMaxDynamicSharedMemorySize, ATTN_SMEM);

    dim3 bb(256);

    // Pre-round inputs to tf32
    preround3<<<dim3(2048, 1, 3), bb>>>(query, key, value, rq, rk, rv);
    WArgs wa; wa.in[0] = Wq; wa.in[1] = Wk; wa.in[2] = Wv; wa.in[3] = Wg; wa.in[4] = Wo;
    preround_w<<<dim3(256, 1, 5), bb>>>(wa, w);

    // Batched Q/K/V/gate projections
    GemmArgs p;
    p.A[0] = rq; p.W[0] = w;              p.C[0] = qf; p.mode[0] = MODE_PHI;
    p.A[1] = rk; p.W[1] = w + 262144;     p.C[1] = kf; p.mode[1] = MODE_PHI;
    p.A[2] = rv; p.W[2] = w + 2*262144;   p.C[2] = vg; p.mode[2] = MODE_RAW;
    p.A[3] = rv; p.W[3] = w + 3*262144;   p.C[3] = gt; p.mode[3] = MODE_RAW;
    gemm128<<<dim3(4, 32, 4), bb, GSM>>>(p);

    // Gate (in place on vg), tf32-rounded
    gate_k<<<1024, bb>>>(vg, gt, bg);

    // Per-chunk K^T V + k sums
    ktv_k<<<dim3(NC, HH, BB), bb>>>(kf, vg, ktv, ksum);

    // Exclusive state prefix
    state_k<<<512, bb>>>(ktv, st);

    // inv denominators
    inv_k<<<dim3(NC, HH, BB), bb>>>(qf, kf, ksum, invd);

    // Attention (paired row tiles)
    attn_tc<<<dim3(NC/2, HH, BB), bb, ATTN_SMEM>>>(qf, kf, vg, st, invd, ov, att);

    // Output projection
    GemmArgs po;
    for (int i = 0; i < 4; i++) { po.A[i] = ov; po.W[i] = w + 4*262144; po.C[i] = out; po.mode[i] = MODE_RAW; }
    gemm128<<<dim3(4, 32, 1), bb, GSM>>>(po);
}